// round 5
// baseline (speedup 1.0000x reference)
#include <cuda_runtime.h>

// Neural 2D min-sum LDPC decoder, (3,6)-regular layered graph.
// One CTA per codeword; edge state (3*8192 floats = 96KB) smem-resident for all
// T iterations. msg[l*NV + v]: v2c after var phase, c2v after check phase
// (in-place; per layer each variable belongs to exactly one check).
// Check c, layer l owns edges e = l*NV + 2c + {0,1} (edge_c = i>>1 by construction).

#define NV 8192
#define MC 4096
#define NL 3
#define TPB 1024
#define VPT (NV / TPB)    // 8 consecutive variables per thread
#define CPT (MC / TPB)    // 4 checks per thread (strided)
#define SMEM_BYTES (NL * NV * 4)

__global__ __launch_bounds__(TPB, 1)
void bp_kernel(const float* __restrict__ llr,
               const int*   __restrict__ edge_v,
               const float* __restrict__ beta,
               const float* __restrict__ alpha,
               float* __restrict__ out_f,
               int*   __restrict__ out_i,
               int B, int T, int mode)
{
    extern __shared__ float msg[];   // [NL*NV]

    const int tid = threadIdx.x;
    const int vb  = tid * VPT;       // first of 8 consecutive owned variables

    // Register-resident check->var table (graph fixed across codewords/iters).
    unsigned pk[CPT][NL];
#pragma unroll
    for (int k = 0; k < CPT; k++) {
        int c = tid + k * TPB;
#pragma unroll
        for (int l = 0; l < NL; l++) {
            unsigned v0 = (unsigned)edge_v[l * NV + 2 * c];
            unsigned v1 = (unsigned)edge_v[l * NV + 2 * c + 1];
            pk[k][l] = v0 | (v1 << 16);
        }
    }

    for (int cw = blockIdx.x; cw < B; cw += gridDim.x) {
        // Channel LLRs: 2x float4, coalesced.
        float llrv[VPT];
#pragma unroll
        for (int g = 0; g < VPT / 4; g++) {
            float4 l4 = *(const float4*)(llr + (size_t)cw * NV + vb + 4 * g);
            llrv[4 * g + 0] = l4.x; llrv[4 * g + 1] = l4.y;
            llrv[4 * g + 2] = l4.z; llrv[4 * g + 3] = l4.w;
        }

        // v2c init = llr at each edge (float4 stores per plane).
#pragma unroll
        for (int l = 0; l < NL; l++)
#pragma unroll
            for (int g = 0; g < VPT / 4; g++) {
                float4 s4 = make_float4(llrv[4 * g], llrv[4 * g + 1],
                                        llrv[4 * g + 2], llrv[4 * g + 3]);
                *(float4*)(msg + l * NV + vb + 4 * g) = s4;
            }
        __syncthreads();

        for (int t = 0; t < T; t++) {
            float bt = __ldg(beta + t);
            float at = __ldg(alpha + t);

            // ---------- check phase: v2c -> c2v (in place) ----------
#pragma unroll 1
            for (int k = 0; k < CPT; k++) {
                int vi[6];
#pragma unroll
                for (int l = 0; l < NL; l++) {
                    vi[2 * l]     = (int)(pk[k][l] & 0xFFFFu);
                    vi[2 * l + 1] = (int)(pk[k][l] >> 16);
                }
                unsigned u[6];
#pragma unroll
                for (int p = 0; p < 6; p++)
                    u[p] = __float_as_uint(msg[(p >> 1) * NV + vi[p]]);

                unsigned a0 = u[0] & 0x7fffffffu, a1 = u[1] & 0x7fffffffu;
                unsigned a2 = u[2] & 0x7fffffffu, a3 = u[3] & 0x7fffffffu;
                unsigned a4 = u[4] & 0x7fffffffu, a5 = u[5] & 0x7fffffffu;
                unsigned xs = (u[0] ^ u[1]) ^ (u[2] ^ u[3]) ^ (u[4] ^ u[5]);

                // Multiset 2-min tournament on abs bits (nonneg floats order as ints).
                unsigned lo01 = min(a0, a1), hi01 = max(a0, a1);
                unsigned lo23 = min(a2, a3), hi23 = max(a2, a3);
                unsigned lo45 = min(a4, a5), hi45 = max(a4, a5);
                unsigned m1a  = min(lo01, lo23);
                unsigned m2a  = min(max(lo01, lo23), min(hi01, hi23));
                unsigned m1   = min(m1a, lo45);
                unsigned m2   = min(max(m1a, lo45), min(m2a, hi45));
                // exact-zero v2c => reference sign product = 0 => all c2v = 0
                m2 = (m1 == 0u) ? 0u : m2;

                unsigned b1 = __float_as_uint(bt * __uint_as_float(m1));
                unsigned b2 = __float_as_uint(bt * __uint_as_float(m2));

                unsigned as[6] = {a0, a1, a2, a3, a4, a5};
#pragma unroll
                for (int p = 0; p < 6; p++) {
                    unsigned mag = (as[p] == m1) ? b2 : b1;   // excl_min (ties => b1==b2)
                    unsigned res = mag ^ ((xs ^ u[p]) & 0x80000000u);
                    msg[(p >> 1) * NV + vi[p]] = __uint_as_float(res);
                }
            }
            __syncthreads();

            // ---------- variable phase: c2v -> v2c (skip after last iter) ----------
            if (t + 1 < T) {
#pragma unroll
                for (int g = 0; g < VPT / 4; g++) {
                    int v = vb + 4 * g;
                    float4 c0 = *(float4*)(msg + v);
                    float4 c1 = *(float4*)(msg + NV + v);
                    float4 c2 = *(float4*)(msg + 2 * NV + v);
                    float4 n0, n1, n2;
                    {
                        float sv = c0.x + c1.x + c2.x, b = llrv[4 * g + 0];
                        n0.x = b + at * (sv - c0.x); n1.x = b + at * (sv - c1.x); n2.x = b + at * (sv - c2.x);
                    }
                    {
                        float sv = c0.y + c1.y + c2.y, b = llrv[4 * g + 1];
                        n0.y = b + at * (sv - c0.y); n1.y = b + at * (sv - c1.y); n2.y = b + at * (sv - c2.y);
                    }
                    {
                        float sv = c0.z + c1.z + c2.z, b = llrv[4 * g + 2];
                        n0.z = b + at * (sv - c0.z); n1.z = b + at * (sv - c1.z); n2.z = b + at * (sv - c2.z);
                    }
                    {
                        float sv = c0.w + c1.w + c2.w, b = llrv[4 * g + 3];
                        n0.w = b + at * (sv - c0.w); n1.w = b + at * (sv - c1.w); n2.w = b + at * (sv - c2.w);
                    }
                    *(float4*)(msg + v)          = n0;
                    *(float4*)(msg + NV + v)     = n1;
                    *(float4*)(msg + 2 * NV + v) = n2;
                }
                __syncthreads();
            }
        }

        // ---------- posterior + hard decision ----------
#pragma unroll
        for (int g = 0; g < VPT / 4; g++) {
            int v = vb + 4 * g;
            float4 c0 = *(float4*)(msg + v);
            float4 c1 = *(float4*)(msg + NV + v);
            float4 c2 = *(float4*)(msg + 2 * NV + v);
            float post[4];
            post[0] = llrv[4 * g + 0] + (c0.x + c1.x + c2.x);
            post[1] = llrv[4 * g + 1] + (c0.y + c1.y + c2.y);
            post[2] = llrv[4 * g + 2] + (c0.z + c1.z + c2.z);
            post[3] = llrv[4 * g + 3] + (c0.w + c1.w + c2.w);
            size_t idx = (size_t)cw * NV + v;
            if (mode) {
#pragma unroll
                for (int j = 0; j < 4; j++) {
                    out_f[idx + j] = (post[j] < 0.0f) ? 1.0f : 0.0f;
                    out_f[(size_t)B * NV + idx + j] = post[j];
                }
            } else {
#pragma unroll
                for (int j = 0; j < 4; j++)
                    out_i[idx + j] = (post[j] < 0.0f) ? 1 : 0;
            }
        }
        __syncthreads();   // protect msg before next codeword reuses it
    }
}

extern "C" void kernel_launch(void* const* d_in, const int* in_sizes, int n_in,
                              void* d_out, int out_size) {
    // metadata order: llr [B,N] f32, edge_v [E] i32, edge_c [E] i32 (implicit),
    // beta [T] f32, alpha [T] f32
    const float* llr    = (const float*)d_in[0];
    const int*   edge_v = (const int*)  d_in[1];
    const float* beta   = (const float*)d_in[3];
    const float* alpha  = (const float*)d_in[4];

    int B = in_sizes[0] / NV;
    int T = in_sizes[3];
    int mode = (out_size >= 2 * B * NV) ? 1 : 0;

    cudaFuncSetAttribute((const void*)bp_kernel,
                         cudaFuncAttributeMaxDynamicSharedMemorySize, SMEM_BYTES);
    bp_kernel<<<B, TPB, SMEM_BYTES>>>(llr, edge_v, beta, alpha,
                                      (float*)d_out, (int*)d_out, B, T, mode);
}